// round 15
// baseline (speedup 1.0000x reference)
#include <cuda_runtime.h>
#include <cuda_fp16.h>
#include <cstdint>

// ---------------------------------------------------------------------------
// MultiHeadAttention, fp16 tensor cores (m16n8k16, fp32 accum) + ldmatrix +
// cp.async.  B=2, S=2048, D=1024, H=16, d=64.
// R15: GEMM loop cadence reverted to R11; warp tile widened to 64x64
// (4 warps / 128 threads per CTA) to double per-warp MMA density.
// Attention unchanged from R11.
// ---------------------------------------------------------------------------

constexpr int S_LEN = 2048;
constexpr int DM    = 1024;
constexpr int NH    = 16;
constexpr int HD    = 64;
constexpr int BATCH = 2;
constexpr int MROWS = BATCH * S_LEN;   // 4096

__device__ __half g_xh [(size_t)MROWS * DM];
__device__ __half g_wh [(size_t)4 * DM * DM];
__device__ __half g_q  [(size_t)BATCH * NH * S_LEN * HD];   // pre-scaled 1/8
__device__ __half g_k  [(size_t)BATCH * NH * S_LEN * HD];
__device__ __half g_v  [(size_t)BATCH * NH * S_LEN * HD];
__device__ __half g_ctx[(size_t)MROWS * DM];

__device__ __forceinline__ void mma_f16(float* c, const uint32_t* a, const uint32_t* b) {
    asm volatile(
        "mma.sync.aligned.m16n8k16.row.col.f32.f16.f16.f32 "
        "{%0,%1,%2,%3}, {%4,%5,%6,%7}, {%8,%9}, {%0,%1,%2,%3};"
        : "+f"(c[0]), "+f"(c[1]), "+f"(c[2]), "+f"(c[3])
        : "r"(a[0]), "r"(a[1]), "r"(a[2]), "r"(a[3]), "r"(b[0]), "r"(b[1]));
}
__device__ __forceinline__ void ldsm_x4(uint32_t* r, uint32_t addr) {
    asm volatile("ldmatrix.sync.aligned.m8n8.x4.shared.b16 {%0,%1,%2,%3}, [%4];"
        : "=r"(r[0]), "=r"(r[1]), "=r"(r[2]), "=r"(r[3]) : "r"(addr));
}
__device__ __forceinline__ void ldsm_x4_t(uint32_t* r, uint32_t addr) {
    asm volatile("ldmatrix.sync.aligned.m8n8.x4.trans.shared.b16 {%0,%1,%2,%3}, [%4];"
        : "=r"(r[0]), "=r"(r[1]), "=r"(r[2]), "=r"(r[3]) : "r"(addr));
}
__device__ __forceinline__ void cp_async16(uint32_t smem, const void* g) {
    asm volatile("cp.async.cg.shared.global [%0], [%1], 16;" :: "r"(smem), "l"(g));
}
__device__ __forceinline__ void cp_commit() { asm volatile("cp.async.commit_group;"); }
template<int N> __device__ __forceinline__ void cp_wait() {
    asm volatile("cp.async.wait_group %0;" :: "n"(N));
}
__device__ __forceinline__ uint32_t pack_h2(float a, float b) {
    __half2 h = __floats2half2_rn(a, b);
    return *reinterpret_cast<uint32_t*>(&h);
}

// ---------------------------------------------------------------------------
// Convert x + weights to fp16.  8 floats per thread.
// ---------------------------------------------------------------------------
__global__ void __launch_bounds__(256)
convert_kernel(const float* __restrict__ x,  const float* __restrict__ wq,
               const float* __restrict__ wk, const float* __restrict__ wv,
               const float* __restrict__ wo)
{
    constexpr size_t NX = (size_t)MROWS * DM;      // 4M
    constexpr size_t NW = (size_t)DM * DM;         // 1M
    const size_t i8 = ((size_t)blockIdx.x * 256 + threadIdx.x) * 8;
    const float* src;
    __half* dst;
    if (i8 < NX) { src = x + i8; dst = g_xh + i8; }
    else {
        const size_t r = i8 - NX;
        const int t = (int)(r / NW);
        const size_t off = r % NW;
        src = ((t == 0) ? wq : (t == 1) ? wk : (t == 2) ? wv : wo) + off;
        dst = g_wh + (size_t)t * NW + off;
    }
    float4 a = *(const float4*)(src);
    float4 b = *(const float4*)(src + 4);
    __half2 h[4];
    h[0] = __floats2half2_rn(a.x, a.y); h[1] = __floats2half2_rn(a.z, a.w);
    h[2] = __floats2half2_rn(b.x, b.y); h[3] = __floats2half2_rn(b.z, b.w);
    *(uint4*)dst = *(uint4*)h;
}

// ---------------------------------------------------------------------------
// GEMM fp16: C[4096,1024] = A @ W + bias.  128x128 CTA tile, 4 warps (2x2),
// warp 64x64, BK=32 x 4 stages, R11 cadence: sync -> issue kt+3 -> wait kt
// -> compute kt.  MODE 0: fp32 row-major out.  MODE 1: merged QKV, half
// head-split out, z==0 scaled 1/8.
// ---------------------------------------------------------------------------
struct GemmSmem {
    __half A[4][128][40];     // pad 40: ldmatrix conflict-free
    __half B[4][32][136];     // pad 136: conflict-free
};

template<int MODE>
__global__ void __launch_bounds__(128)
gemm_f16_kernel(const __half* __restrict__ Ag, const __half* __restrict__ Wall,
                const float* __restrict__ b0, const float* __restrict__ b1,
                const float* __restrict__ b2,
                __half* __restrict__ o0, __half* __restrict__ o1,
                __half* __restrict__ o2, float* __restrict__ fout)
{
    constexpr int K = DM, N = DM;
    extern __shared__ char smem_raw[];
    GemmSmem& s = *reinterpret_cast<GemmSmem*>(smem_raw);

    const int tid  = threadIdx.x;
    const int warp = tid >> 5, lane = tid & 31;
    const int g    = lane >> 2, tg = lane & 3;
    const int wr   = warp >> 1;            // 0..1  (row half)
    const int wc   = warp & 1;             // 0..1  (col half)
    const int brow = blockIdx.y * 128;
    const int bcol = blockIdx.x * 128;
    const int z    = (MODE == 1) ? blockIdx.z : 0;

    const __half* W    = (MODE == 1) ? (Wall + (size_t)z * DM * DM) : Wall;
    const float* bias  = (MODE == 1) ? ((z == 0) ? b0 : (z == 1) ? b1 : b2) : b0;
    __half* outh       = (MODE == 1) ? ((z == 0) ? o0 : (z == 1) ? o1 : o2) : o0;
    const float oscale = (MODE == 1 && z == 0) ? 0.125f : 1.0f;

    const uint32_t sA = (uint32_t)__cvta_generic_to_shared(&s.A[0][0][0]);
    const uint32_t sB = (uint32_t)__cvta_generic_to_shared(&s.B[0][0][0]);
    constexpr uint32_t A_STAGE = 128 * 40 * 2;   // 10240
    constexpr uint32_t B_STAGE = 32 * 136 * 2;   // 8704

    // cp.async: A 512 chunks, B 512 chunks; 4+4 per thread (128 threads)
    auto issue = [&](int kt) {
        const uint32_t st = (uint32_t)(kt & 3);
#pragma unroll
        for (int i = 0; i < 4; i++) {
            const int ca = tid * 4 + i, row = ca >> 2, c8 = (ca & 3) * 8;
            cp_async16(sA + st * A_STAGE + (uint32_t)(row * 40 + c8) * 2,
                       Ag + (size_t)(brow + row) * K + kt * 32 + c8);
            const int cb = tid * 4 + i, rb = cb >> 4, n8 = (cb & 15) * 8;
            cp_async16(sB + st * B_STAGE + (uint32_t)(rb * 136 + n8) * 2,
                       W + (size_t)(kt * 32 + rb) * N + bcol + n8);
        }
    };

    float acc[4][8][4];
#pragma unroll
    for (int mt = 0; mt < 4; mt++)
#pragma unroll
        for (int nt = 0; nt < 8; nt++)
#pragma unroll
            for (int i = 0; i < 4; i++) acc[mt][nt][i] = 0.f;

    issue(0); cp_commit();
    issue(1); cp_commit();
    issue(2); cp_commit();

    constexpr int NCHUNK = K / 32;         // 32
    for (int kt = 0; kt < NCHUNK; kt++) {
        cp_wait<2>();
        __syncthreads();
        if (kt + 3 < NCHUNK) issue(kt + 3);
        cp_commit();

        const uint32_t st = (uint32_t)(kt & 3);
        const uint32_t aBase = sA + st * A_STAGE;
        const uint32_t bBase = sB + st * B_STAGE;

#pragma unroll
        for (int ks = 0; ks < 2; ks++) {
            uint32_t a[4][4];
#pragma unroll
            for (int mt = 0; mt < 4; mt++) {
                const int r = wr * 64 + mt * 16 + (lane & 15);
                const int c = ks * 16 + (lane >> 4) * 8;
                ldsm_x4(a[mt], aBase + (uint32_t)(r * 40 + c) * 2);
            }
            uint32_t b[8][2];
#pragma unroll
            for (int ntp = 0; ntp < 4; ntp++) {
                uint32_t bb[4];
                const int rk = ks * 16 + (lane & 15);
                const int nn = wc * 64 + ntp * 16 + (lane >> 4) * 8;
                ldsm_x4_t(bb, bBase + (uint32_t)(rk * 136 + nn) * 2);
                b[2 * ntp][0] = bb[0]; b[2 * ntp][1] = bb[1];
                b[2 * ntp + 1][0] = bb[2]; b[2 * ntp + 1][1] = bb[3];
            }
#pragma unroll
            for (int mt = 0; mt < 4; mt++)
#pragma unroll
                for (int nt = 0; nt < 8; nt++)
                    mma_f16(acc[mt][nt], a[mt], b[nt]);
        }
    }

    // epilogue
#pragma unroll
    for (int mt = 0; mt < 4; mt++) {
#pragma unroll
        for (int nt = 0; nt < 8; nt++) {
#pragma unroll
            for (int half = 0; half < 2; half++) {
                const int m = brow + wr * 64 + mt * 16 + g + half * 8;
                const int n = bcol + wc * 64 + nt * 8 + 2 * tg;
                const float v0 = (acc[mt][nt][half * 2 + 0] + bias[n])     * oscale;
                const float v1 = (acc[mt][nt][half * 2 + 1] + bias[n + 1]) * oscale;
                if (MODE == 0) {
                    *(float2*)&fout[(size_t)m * N + n] = make_float2(v0, v1);
                } else {
                    const int bb = m >> 11, sidx = m & 2047;
                    const int h  = n >> 6,  dd = n & 63;
                    *(uint32_t*)&outh[(((size_t)(bb * NH + h) * S_LEN) + sidx) * HD + dd]
                        = pack_h2(v0, v1);
                }
            }
        }
    }
}

// ---------------------------------------------------------------------------
// Flash attention fp16.  Block = 128 q x head x batch, 8 warps; each warp
// owns 16 q-rows x FULL kv tile -> softmax entirely warp-local.
// One __syncthreads per KV tile.  KV tile 64, cp.async double buffer.
// (Unchanged from R11.)
// ---------------------------------------------------------------------------
struct AttnSmem {
    __half K[2][64][72];
    __half V[2][64][72];
};

__global__ void __launch_bounds__(256, 2)
attn_f16_kernel(const __half* __restrict__ Q, const __half* __restrict__ Km,
                const __half* __restrict__ Vm, __half* __restrict__ ctx)
{
    __shared__ AttnSmem s;

    const int tid  = threadIdx.x;
    const int warp = tid >> 5, lane = tid & 31;
    const int g    = lane >> 2, tg = lane & 3;
    const int qt0  = blockIdx.x * 128;
    const int h    = blockIdx.y;
    const int b    = blockIdx.z;
    const size_t head_base = (size_t)(b * NH + h) * S_LEN * HD;

    const __half* Kg = Km + head_base;
    const __half* Vg = Vm + head_base;

    uint32_t qa[4][4];
    {
        const __half* q0 = Q + head_base + (size_t)(qt0 + warp * 16 + g) * HD;
        const __half* q1 = q0 + 8 * HD;
#pragma unroll
        for (int ks = 0; ks < 4; ks++) {
            qa[ks][0] = *(const uint32_t*)&q0[ks * 16 + 2 * tg];
            qa[ks][1] = *(const uint32_t*)&q1[ks * 16 + 2 * tg];
            qa[ks][2] = *(const uint32_t*)&q0[ks * 16 + 8 + 2 * tg];
            qa[ks][3] = *(const uint32_t*)&q1[ks * 16 + 8 + 2 * tg];
        }
    }

    float m0 = -1e30f, m1 = -1e30f;
    float l0 = 0.f, l1 = 0.f;
    float oa[8][4];
#pragma unroll
    for (int nt = 0; nt < 8; nt++)
#pragma unroll
        for (int i = 0; i < 4; i++) oa[nt][i] = 0.f;

    const uint32_t sK = (uint32_t)__cvta_generic_to_shared(&s.K[0][0][0]);
    const uint32_t sV = (uint32_t)__cvta_generic_to_shared(&s.V[0][0][0]);
    constexpr uint32_t KV_STAGE = 64 * 72 * 2;
    constexpr int NTILE = S_LEN / 64;

    auto issue = [&](int kt) {
        const uint32_t st = (uint32_t)(kt & 1);
        const int base = kt * 64;
#pragma unroll
        for (int i = 0; i < 2; i++) {
            const int idx = tid * 2 + i;
            const int row = idx >> 3, c8 = (idx & 7) * 8;
            const size_t goff = (size_t)(base + row) * HD + c8;
            const uint32_t soff = (uint32_t)(row * 72 + c8) * 2;
            cp_async16(sK + st * KV_STAGE + soff, Kg + goff);
            cp_async16(sV + st * KV_STAGE + soff, Vg + goff);
        }
    };

    issue(0); cp_commit();

    for (int kt = 0; kt < NTILE; kt++) {
        cp_wait<0>();
        __syncthreads();
        if (kt + 1 < NTILE) issue(kt + 1);
        cp_commit();

        const uint32_t st = (uint32_t)(kt & 1);
        const uint32_t kBase = sK + st * KV_STAGE;
        const uint32_t vBase = sV + st * KV_STAGE;

        float sa[8][4];
#pragma unroll
        for (int nt = 0; nt < 8; nt++)
#pragma unroll
            for (int i = 0; i < 4; i++) sa[nt][i] = 0.f;
#pragma unroll
        for (int p = 0; p < 2; p++) {
#pragma unroll
            for (int nt = 0; nt < 8; nt++) {
                uint32_t kb[4];
                const int kvr = nt * 8 + (lane & 7);
                const int d   = p * 32 + (lane >> 3) * 8;
                ldsm_x4(kb, kBase + (uint32_t)(kvr * 72 + d) * 2);
                mma_f16(sa[nt], qa[2 * p],     kb);
                mma_f16(sa[nt], qa[2 * p + 1], kb + 2);
            }
        }

        float pm0 = -1e30f, pm1 = -1e30f;
#pragma unroll
        for (int nt = 0; nt < 8; nt++) {
            pm0 = fmaxf(pm0, fmaxf(sa[nt][0], sa[nt][1]));
            pm1 = fmaxf(pm1, fmaxf(sa[nt][2], sa[nt][3]));
        }
        pm0 = fmaxf(pm0, __shfl_xor_sync(0xffffffffu, pm0, 1));
        pm0 = fmaxf(pm0, __shfl_xor_sync(0xffffffffu, pm0, 2));
        pm1 = fmaxf(pm1, __shfl_xor_sync(0xffffffffu, pm1, 1));
        pm1 = fmaxf(pm1, __shfl_xor_sync(0xffffffffu, pm1, 2));

        const float mnew0 = fmaxf(m0, pm0);
        const float mnew1 = fmaxf(m1, pm1);
        const float sc0 = __expf(m0 - mnew0);
        const float sc1 = __expf(m1 - mnew1);

        float ps0 = 0.f, ps1 = 0.f;
#pragma unroll
        for (int nt = 0; nt < 8; nt++) {
            sa[nt][0] = __expf(sa[nt][0] - mnew0);
            sa[nt][1] = __expf(sa[nt][1] - mnew0);
            sa[nt][2] = __expf(sa[nt][2] - mnew1);
            sa[nt][3] = __expf(sa[nt][3] - mnew1);
            ps0 += sa[nt][0] + sa[nt][1];
            ps1 += sa[nt][2] + sa[nt][3];
        }
        ps0 += __shfl_xor_sync(0xffffffffu, ps0, 1);
        ps0 += __shfl_xor_sync(0xffffffffu, ps0, 2);
        ps1 += __shfl_xor_sync(0xffffffffu, ps1, 1);
        ps1 += __shfl_xor_sync(0xffffffffu, ps1, 2);

        l0 = l0 * sc0 + ps0;
        l1 = l1 * sc1 + ps1;
        m0 = mnew0; m1 = mnew1;
#pragma unroll
        for (int nt = 0; nt < 8; nt++) {
            oa[nt][0] *= sc0; oa[nt][1] *= sc0;
            oa[nt][2] *= sc1; oa[nt][3] *= sc1;
        }

#pragma unroll
        for (int p = 0; p < 4; p++) {
            uint32_t pa[4];
            pa[0] = pack_h2(sa[2 * p][0],     sa[2 * p][1]);
            pa[1] = pack_h2(sa[2 * p][2],     sa[2 * p][3]);
            pa[2] = pack_h2(sa[2 * p + 1][0], sa[2 * p + 1][1]);
            pa[3] = pack_h2(sa[2 * p + 1][2], sa[2 * p + 1][3]);
#pragma unroll
            for (int ntp = 0; ntp < 4; ntp++) {
                uint32_t vb[4];
                const int kvr = p * 16 + (lane & 15);
                const int d   = ntp * 16 + (lane >> 4) * 8;
                ldsm_x4_t(vb, vBase + (uint32_t)(kvr * 72 + d) * 2);
                mma_f16(oa[2 * ntp],     pa, vb);
                mma_f16(oa[2 * ntp + 1], pa, vb + 2);
            }
        }
    }

    const float inv0 = 1.f / l0;
    const float inv1 = 1.f / l1;
    __half* c0p = ctx + ((size_t)(b * S_LEN) + qt0 + warp * 16 + g) * DM + h * HD;
    __half* c1p = c0p + 8 * DM;
#pragma unroll
    for (int nt = 0; nt < 8; nt++) {
        const int c = nt * 8 + 2 * tg;
        *(uint32_t*)&c0p[c] = pack_h2(oa[nt][0] * inv0, oa[nt][1] * inv0);
        *(uint32_t*)&c1p[c] = pack_h2(oa[nt][2] * inv1, oa[nt][3] * inv1);
    }
}

// ---------------------------------------------------------------------------
extern "C" void kernel_launch(void* const* d_in, const int* in_sizes, int n_in,
                              void* d_out, int out_size)
{
    const float* x  = (const float*)d_in[0];
    const float* wq = (const float*)d_in[1];
    const float* bq = (const float*)d_in[2];
    const float* wk = (const float*)d_in[3];
    const float* bk = (const float*)d_in[4];
    const float* wv = (const float*)d_in[5];
    const float* bv = (const float*)d_in[6];
    const float* wo = (const float*)d_in[7];
    const float* bo = (const float*)d_in[8];
    float* out = (float*)d_out;

    __half *xh, *wh, *q, *k, *v, *ctx;
    cudaGetSymbolAddress((void**)&xh,  g_xh);
    cudaGetSymbolAddress((void**)&wh,  g_wh);
    cudaGetSymbolAddress((void**)&q,   g_q);
    cudaGetSymbolAddress((void**)&k,   g_k);
    cudaGetSymbolAddress((void**)&v,   g_v);
    cudaGetSymbolAddress((void**)&ctx, g_ctx);

    constexpr int GSM = (int)sizeof(GemmSmem);
    cudaFuncSetAttribute(gemm_f16_kernel<0>,
                         cudaFuncAttributeMaxDynamicSharedMemorySize, GSM);
    cudaFuncSetAttribute(gemm_f16_kernel<1>,
                         cudaFuncAttributeMaxDynamicSharedMemorySize, GSM);

    // 1) fp16 conversion
    constexpr int NCONV = (int)(((size_t)MROWS * DM + 4 * (size_t)DM * DM) / 8);
    convert_kernel<<<NCONV / 256, 256>>>(x, wq, wk, wv, wo);

    // 2) merged QKV projection (128 threads per CTA)
    dim3 gqkv(DM / 128, MROWS / 128, 3);
    gemm_f16_kernel<1><<<gqkv, 128, GSM>>>(xh, wh, bq, bk, bv, q, k, v, nullptr);

    // 3) flash attention (128 q-rows per block)
    dim3 ga(S_LEN / 128, NH, BATCH);
    attn_f16_kernel<<<ga, 256>>>(q, k, v, ctx);

    // 4) output projection
    dim3 gg(DM / 128, MROWS / 128);
    gemm_f16_kernel<0><<<gg, 128, GSM>>>(ctx, wh + (size_t)3 * DM * DM,
                                         bo, nullptr, nullptr,
                                         nullptr, nullptr, nullptr, out);
}

// round 16
// speedup vs baseline: 1.0790x; 1.0790x over previous
#include <cuda_runtime.h>
#include <cuda_fp16.h>
#include <cstdint>

// ---------------------------------------------------------------------------
// MultiHeadAttention, fp16 tensor cores (m16n8k16, fp32 accum) + ldmatrix +
// cp.async.  B=2, S=2048, D=1024, H=16, d=64.
// R16: GEMM re-tiled to 64x128 CTAs (128 thr, 4 warps, warp 32x64),
// 55.3 KB smem -> 4 CTAs/SM: 16 warps/SM across 4 independent barrier
// domains (attention-style residency).  R11 loop cadence.  Attention = R11.
// ---------------------------------------------------------------------------

constexpr int S_LEN = 2048;
constexpr int DM    = 1024;
constexpr int NH    = 16;
constexpr int HD    = 64;
constexpr int BATCH = 2;
constexpr int MROWS = BATCH * S_LEN;   // 4096

__device__ __half g_xh [(size_t)MROWS * DM];
__device__ __half g_wh [(size_t)4 * DM * DM];
__device__ __half g_q  [(size_t)BATCH * NH * S_LEN * HD];   // pre-scaled 1/8
__device__ __half g_k  [(size_t)BATCH * NH * S_LEN * HD];
__device__ __half g_v  [(size_t)BATCH * NH * S_LEN * HD];
__device__ __half g_ctx[(size_t)MROWS * DM];

__device__ __forceinline__ void mma_f16(float* c, const uint32_t* a, const uint32_t* b) {
    asm volatile(
        "mma.sync.aligned.m16n8k16.row.col.f32.f16.f16.f32 "
        "{%0,%1,%2,%3}, {%4,%5,%6,%7}, {%8,%9}, {%0,%1,%2,%3};"
        : "+f"(c[0]), "+f"(c[1]), "+f"(c[2]), "+f"(c[3])
        : "r"(a[0]), "r"(a[1]), "r"(a[2]), "r"(a[3]), "r"(b[0]), "r"(b[1]));
}
__device__ __forceinline__ void ldsm_x4(uint32_t* r, uint32_t addr) {
    asm volatile("ldmatrix.sync.aligned.m8n8.x4.shared.b16 {%0,%1,%2,%3}, [%4];"
        : "=r"(r[0]), "=r"(r[1]), "=r"(r[2]), "=r"(r[3]) : "r"(addr));
}
__device__ __forceinline__ void ldsm_x4_t(uint32_t* r, uint32_t addr) {
    asm volatile("ldmatrix.sync.aligned.m8n8.x4.trans.shared.b16 {%0,%1,%2,%3}, [%4];"
        : "=r"(r[0]), "=r"(r[1]), "=r"(r[2]), "=r"(r[3]) : "r"(addr));
}
__device__ __forceinline__ void cp_async16(uint32_t smem, const void* g) {
    asm volatile("cp.async.cg.shared.global [%0], [%1], 16;" :: "r"(smem), "l"(g));
}
__device__ __forceinline__ void cp_commit() { asm volatile("cp.async.commit_group;"); }
template<int N> __device__ __forceinline__ void cp_wait() {
    asm volatile("cp.async.wait_group %0;" :: "n"(N));
}
__device__ __forceinline__ uint32_t pack_h2(float a, float b) {
    __half2 h = __floats2half2_rn(a, b);
    return *reinterpret_cast<uint32_t*>(&h);
}

// ---------------------------------------------------------------------------
// Convert x + weights to fp16.  8 floats per thread.
// ---------------------------------------------------------------------------
__global__ void __launch_bounds__(256)
convert_kernel(const float* __restrict__ x,  const float* __restrict__ wq,
               const float* __restrict__ wk, const float* __restrict__ wv,
               const float* __restrict__ wo)
{
    constexpr size_t NX = (size_t)MROWS * DM;      // 4M
    constexpr size_t NW = (size_t)DM * DM;         // 1M
    const size_t i8 = ((size_t)blockIdx.x * 256 + threadIdx.x) * 8;
    const float* src;
    __half* dst;
    if (i8 < NX) { src = x + i8; dst = g_xh + i8; }
    else {
        const size_t r = i8 - NX;
        const int t = (int)(r / NW);
        const size_t off = r % NW;
        src = ((t == 0) ? wq : (t == 1) ? wk : (t == 2) ? wv : wo) + off;
        dst = g_wh + (size_t)t * NW + off;
    }
    float4 a = *(const float4*)(src);
    float4 b = *(const float4*)(src + 4);
    __half2 h[4];
    h[0] = __floats2half2_rn(a.x, a.y); h[1] = __floats2half2_rn(a.z, a.w);
    h[2] = __floats2half2_rn(b.x, b.y); h[3] = __floats2half2_rn(b.z, b.w);
    *(uint4*)dst = *(uint4*)h;
}

// ---------------------------------------------------------------------------
// GEMM fp16: C[4096,1024] = A @ W + bias.  64x128 CTA tile, 4 warps (2x2),
// warp 32x64, BK=32 x 4 stages, R11 cadence: sync -> issue kt+3 -> wait kt
// -> compute kt.  4 CTAs/SM.  MODE 0: fp32 row-major out.  MODE 1: merged
// QKV, half head-split out, z==0 scaled 1/8.
// ---------------------------------------------------------------------------
struct GemmSmem {
    __half A[4][64][40];      // 5120 B/stage; pad 40: ldmatrix conflict-free
    __half B[4][32][136];     // 8704 B/stage; pad 136: conflict-free
};

template<int MODE>
__global__ void __launch_bounds__(128, 4)
gemm_f16_kernel(const __half* __restrict__ Ag, const __half* __restrict__ Wall,
                const float* __restrict__ b0, const float* __restrict__ b1,
                const float* __restrict__ b2,
                __half* __restrict__ o0, __half* __restrict__ o1,
                __half* __restrict__ o2, float* __restrict__ fout)
{
    constexpr int K = DM, N = DM;
    extern __shared__ char smem_raw[];
    GemmSmem& s = *reinterpret_cast<GemmSmem*>(smem_raw);

    const int tid  = threadIdx.x;
    const int warp = tid >> 5, lane = tid & 31;
    const int g    = lane >> 2, tg = lane & 3;
    const int wr   = warp >> 1;            // 0..1  (32-row half)
    const int wc   = warp & 1;             // 0..1  (64-col half)
    const int brow = blockIdx.y * 64;
    const int bcol = blockIdx.x * 128;
    const int z    = (MODE == 1) ? blockIdx.z : 0;

    const __half* W    = (MODE == 1) ? (Wall + (size_t)z * DM * DM) : Wall;
    const float* bias  = (MODE == 1) ? ((z == 0) ? b0 : (z == 1) ? b1 : b2) : b0;
    __half* outh       = (MODE == 1) ? ((z == 0) ? o0 : (z == 1) ? o1 : o2) : o0;
    const float oscale = (MODE == 1 && z == 0) ? 0.125f : 1.0f;

    const uint32_t sA = (uint32_t)__cvta_generic_to_shared(&s.A[0][0][0]);
    const uint32_t sB = (uint32_t)__cvta_generic_to_shared(&s.B[0][0][0]);
    constexpr uint32_t A_STAGE = 64 * 40 * 2;    // 5120
    constexpr uint32_t B_STAGE = 32 * 136 * 2;   // 8704

    // cp.async per chunk: A 256 x 16B chunks (2/thread), B 512 (4/thread)
    auto issue = [&](int kt) {
        const uint32_t st = (uint32_t)(kt & 3);
#pragma unroll
        for (int i = 0; i < 2; i++) {
            const int ca = tid * 2 + i, row = ca >> 2, c8 = (ca & 3) * 8;
            cp_async16(sA + st * A_STAGE + (uint32_t)(row * 40 + c8) * 2,
                       Ag + (size_t)(brow + row) * K + kt * 32 + c8);
        }
#pragma unroll
        for (int i = 0; i < 4; i++) {
            const int cb = tid * 4 + i, rb = cb >> 4, n8 = (cb & 15) * 8;
            cp_async16(sB + st * B_STAGE + (uint32_t)(rb * 136 + n8) * 2,
                       W + (size_t)(kt * 32 + rb) * N + bcol + n8);
        }
    };

    float acc[2][8][4];
#pragma unroll
    for (int mt = 0; mt < 2; mt++)
#pragma unroll
        for (int nt = 0; nt < 8; nt++)
#pragma unroll
            for (int i = 0; i < 4; i++) acc[mt][nt][i] = 0.f;

    issue(0); cp_commit();
    issue(1); cp_commit();
    issue(2); cp_commit();

    constexpr int NCHUNK = K / 32;         // 32
    for (int kt = 0; kt < NCHUNK; kt++) {
        cp_wait<2>();
        __syncthreads();
        if (kt + 3 < NCHUNK) issue(kt + 3);
        cp_commit();

        const uint32_t st = (uint32_t)(kt & 3);
        const uint32_t aBase = sA + st * A_STAGE;
        const uint32_t bBase = sB + st * B_STAGE;

#pragma unroll
        for (int ks = 0; ks < 2; ks++) {
            uint32_t a[2][4];
#pragma unroll
            for (int mt = 0; mt < 2; mt++) {
                const int r = wr * 32 + mt * 16 + (lane & 15);
                const int c = ks * 16 + (lane >> 4) * 8;
                ldsm_x4(a[mt], aBase + (uint32_t)(r * 40 + c) * 2);
            }
            uint32_t b[8][2];
#pragma unroll
            for (int ntp = 0; ntp < 4; ntp++) {
                uint32_t bb[4];
                const int rk = ks * 16 + (lane & 15);
                const int nn = wc * 64 + ntp * 16 + (lane >> 4) * 8;
                ldsm_x4_t(bb, bBase + (uint32_t)(rk * 136 + nn) * 2);
                b[2 * ntp][0] = bb[0]; b[2 * ntp][1] = bb[1];
                b[2 * ntp + 1][0] = bb[2]; b[2 * ntp + 1][1] = bb[3];
            }
#pragma unroll
            for (int mt = 0; mt < 2; mt++)
#pragma unroll
                for (int nt = 0; nt < 8; nt++)
                    mma_f16(acc[mt][nt], a[mt], b[nt]);
        }
    }

    // epilogue
#pragma unroll
    for (int mt = 0; mt < 2; mt++) {
#pragma unroll
        for (int nt = 0; nt < 8; nt++) {
#pragma unroll
            for (int half = 0; half < 2; half++) {
                const int m = brow + wr * 32 + mt * 16 + g + half * 8;
                const int n = bcol + wc * 64 + nt * 8 + 2 * tg;
                const float v0 = (acc[mt][nt][half * 2 + 0] + bias[n])     * oscale;
                const float v1 = (acc[mt][nt][half * 2 + 1] + bias[n + 1]) * oscale;
                if (MODE == 0) {
                    *(float2*)&fout[(size_t)m * N + n] = make_float2(v0, v1);
                } else {
                    const int bb = m >> 11, sidx = m & 2047;
                    const int h  = n >> 6,  dd = n & 63;
                    *(uint32_t*)&outh[(((size_t)(bb * NH + h) * S_LEN) + sidx) * HD + dd]
                        = pack_h2(v0, v1);
                }
            }
        }
    }
}

// ---------------------------------------------------------------------------
// Flash attention fp16.  Block = 128 q x head x batch, 8 warps; each warp
// owns 16 q-rows x FULL kv tile -> softmax entirely warp-local.
// One __syncthreads per KV tile.  KV tile 64, cp.async double buffer.
// (Unchanged from R11.)
// ---------------------------------------------------------------------------
struct AttnSmem {
    __half K[2][64][72];
    __half V[2][64][72];
};

__global__ void __launch_bounds__(256, 2)
attn_f16_kernel(const __half* __restrict__ Q, const __half* __restrict__ Km,
                const __half* __restrict__ Vm, __half* __restrict__ ctx)
{
    __shared__ AttnSmem s;

    const int tid  = threadIdx.x;
    const int warp = tid >> 5, lane = tid & 31;
    const int g    = lane >> 2, tg = lane & 3;
    const int qt0  = blockIdx.x * 128;
    const int h    = blockIdx.y;
    const int b    = blockIdx.z;
    const size_t head_base = (size_t)(b * NH + h) * S_LEN * HD;

    const __half* Kg = Km + head_base;
    const __half* Vg = Vm + head_base;

    uint32_t qa[4][4];
    {
        const __half* q0 = Q + head_base + (size_t)(qt0 + warp * 16 + g) * HD;
        const __half* q1 = q0 + 8 * HD;
#pragma unroll
        for (int ks = 0; ks < 4; ks++) {
            qa[ks][0] = *(const uint32_t*)&q0[ks * 16 + 2 * tg];
            qa[ks][1] = *(const uint32_t*)&q1[ks * 16 + 2 * tg];
            qa[ks][2] = *(const uint32_t*)&q0[ks * 16 + 8 + 2 * tg];
            qa[ks][3] = *(const uint32_t*)&q1[ks * 16 + 8 + 2 * tg];
        }
    }

    float m0 = -1e30f, m1 = -1e30f;
    float l0 = 0.f, l1 = 0.f;
    float oa[8][4];
#pragma unroll
    for (int nt = 0; nt < 8; nt++)
#pragma unroll
        for (int i = 0; i < 4; i++) oa[nt][i] = 0.f;

    const uint32_t sK = (uint32_t)__cvta_generic_to_shared(&s.K[0][0][0]);
    const uint32_t sV = (uint32_t)__cvta_generic_to_shared(&s.V[0][0][0]);
    constexpr uint32_t KV_STAGE = 64 * 72 * 2;
    constexpr int NTILE = S_LEN / 64;

    auto issue = [&](int kt) {
        const uint32_t st = (uint32_t)(kt & 1);
        const int base = kt * 64;
#pragma unroll
        for (int i = 0; i < 2; i++) {
            const int idx = tid * 2 + i;
            const int row = idx >> 3, c8 = (idx & 7) * 8;
            const size_t goff = (size_t)(base + row) * HD + c8;
            const uint32_t soff = (uint32_t)(row * 72 + c8) * 2;
            cp_async16(sK + st * KV_STAGE + soff, Kg + goff);
            cp_async16(sV + st * KV_STAGE + soff, Vg + goff);
        }
    };

    issue(0); cp_commit();

    for (int kt = 0; kt < NTILE; kt++) {
        cp_wait<0>();
        __syncthreads();
        if (kt + 1 < NTILE) issue(kt + 1);
        cp_commit();

        const uint32_t st = (uint32_t)(kt & 1);
        const uint32_t kBase = sK + st * KV_STAGE;
        const uint32_t vBase = sV + st * KV_STAGE;

        float sa[8][4];
#pragma unroll
        for (int nt = 0; nt < 8; nt++)
#pragma unroll
            for (int i = 0; i < 4; i++) sa[nt][i] = 0.f;
#pragma unroll
        for (int p = 0; p < 2; p++) {
#pragma unroll
            for (int nt = 0; nt < 8; nt++) {
                uint32_t kb[4];
                const int kvr = nt * 8 + (lane & 7);
                const int d   = p * 32 + (lane >> 3) * 8;
                ldsm_x4(kb, kBase + (uint32_t)(kvr * 72 + d) * 2);
                mma_f16(sa[nt], qa[2 * p],     kb);
                mma_f16(sa[nt], qa[2 * p + 1], kb + 2);
            }
        }

        float pm0 = -1e30f, pm1 = -1e30f;
#pragma unroll
        for (int nt = 0; nt < 8; nt++) {
            pm0 = fmaxf(pm0, fmaxf(sa[nt][0], sa[nt][1]));
            pm1 = fmaxf(pm1, fmaxf(sa[nt][2], sa[nt][3]));
        }
        pm0 = fmaxf(pm0, __shfl_xor_sync(0xffffffffu, pm0, 1));
        pm0 = fmaxf(pm0, __shfl_xor_sync(0xffffffffu, pm0, 2));
        pm1 = fmaxf(pm1, __shfl_xor_sync(0xffffffffu, pm1, 1));
        pm1 = fmaxf(pm1, __shfl_xor_sync(0xffffffffu, pm1, 2));

        const float mnew0 = fmaxf(m0, pm0);
        const float mnew1 = fmaxf(m1, pm1);
        const float sc0 = __expf(m0 - mnew0);
        const float sc1 = __expf(m1 - mnew1);

        float ps0 = 0.f, ps1 = 0.f;
#pragma unroll
        for (int nt = 0; nt < 8; nt++) {
            sa[nt][0] = __expf(sa[nt][0] - mnew0);
            sa[nt][1] = __expf(sa[nt][1] - mnew0);
            sa[nt][2] = __expf(sa[nt][2] - mnew1);
            sa[nt][3] = __expf(sa[nt][3] - mnew1);
            ps0 += sa[nt][0] + sa[nt][1];
            ps1 += sa[nt][2] + sa[nt][3];
        }
        ps0 += __shfl_xor_sync(0xffffffffu, ps0, 1);
        ps0 += __shfl_xor_sync(0xffffffffu, ps0, 2);
        ps1 += __shfl_xor_sync(0xffffffffu, ps1, 1);
        ps1 += __shfl_xor_sync(0xffffffffu, ps1, 2);

        l0 = l0 * sc0 + ps0;
        l1 = l1 * sc1 + ps1;
        m0 = mnew0; m1 = mnew1;
#pragma unroll
        for (int nt = 0; nt < 8; nt++) {
            oa[nt][0] *= sc0; oa[nt][1] *= sc0;
            oa[nt][2] *= sc1; oa[nt][3] *= sc1;
        }

#pragma unroll
        for (int p = 0; p < 4; p++) {
            uint32_t pa[4];
            pa[0] = pack_h2(sa[2 * p][0],     sa[2 * p][1]);
            pa[1] = pack_h2(sa[2 * p][2],     sa[2 * p][3]);
            pa[2] = pack_h2(sa[2 * p + 1][0], sa[2 * p + 1][1]);
            pa[3] = pack_h2(sa[2 * p + 1][2], sa[2 * p + 1][3]);
#pragma unroll
            for (int ntp = 0; ntp < 4; ntp++) {
                uint32_t vb[4];
                const int kvr = p * 16 + (lane & 15);
                const int d   = ntp * 16 + (lane >> 4) * 8;
                ldsm_x4_t(vb, vBase + (uint32_t)(kvr * 72 + d) * 2);
                mma_f16(oa[2 * ntp],     pa, vb);
                mma_f16(oa[2 * ntp + 1], pa, vb + 2);
            }
        }
    }

    const float inv0 = 1.f / l0;
    const float inv1 = 1.f / l1;
    __half* c0p = ctx + ((size_t)(b * S_LEN) + qt0 + warp * 16 + g) * DM + h * HD;
    __half* c1p = c0p + 8 * DM;
#pragma unroll
    for (int nt = 0; nt < 8; nt++) {
        const int c = nt * 8 + 2 * tg;
        *(uint32_t*)&c0p[c] = pack_h2(oa[nt][0] * inv0, oa[nt][1] * inv0);
        *(uint32_t*)&c1p[c] = pack_h2(oa[nt][2] * inv1, oa[nt][3] * inv1);
    }
}

// ---------------------------------------------------------------------------
extern "C" void kernel_launch(void* const* d_in, const int* in_sizes, int n_in,
                              void* d_out, int out_size)
{
    const float* x  = (const float*)d_in[0];
    const float* wq = (const float*)d_in[1];
    const float* bq = (const float*)d_in[2];
    const float* wk = (const float*)d_in[3];
    const float* bk = (const float*)d_in[4];
    const float* wv = (const float*)d_in[5];
    const float* bv = (const float*)d_in[6];
    const float* wo = (const float*)d_in[7];
    const float* bo = (const float*)d_in[8];
    float* out = (float*)d_out;

    __half *xh, *wh, *q, *k, *v, *ctx;
    cudaGetSymbolAddress((void**)&xh,  g_xh);
    cudaGetSymbolAddress((void**)&wh,  g_wh);
    cudaGetSymbolAddress((void**)&q,   g_q);
    cudaGetSymbolAddress((void**)&k,   g_k);
    cudaGetSymbolAddress((void**)&v,   g_v);
    cudaGetSymbolAddress((void**)&ctx, g_ctx);

    constexpr int GSM = (int)sizeof(GemmSmem);
    cudaFuncSetAttribute(gemm_f16_kernel<0>,
                         cudaFuncAttributeMaxDynamicSharedMemorySize, GSM);
    cudaFuncSetAttribute(gemm_f16_kernel<1>,
                         cudaFuncAttributeMaxDynamicSharedMemorySize, GSM);

    // 1) fp16 conversion
    constexpr int NCONV = (int)(((size_t)MROWS * DM + 4 * (size_t)DM * DM) / 8);
    convert_kernel<<<NCONV / 256, 256>>>(x, wq, wk, wv, wo);

    // 2) merged QKV projection (64-row CTA tiles)
    dim3 gqkv(DM / 128, MROWS / 64, 3);    // (8, 64, 3)
    gemm_f16_kernel<1><<<gqkv, 128, GSM>>>(xh, wh, bq, bk, bv, q, k, v, nullptr);

    // 3) flash attention (128 q-rows per block)
    dim3 ga(S_LEN / 128, NH, BATCH);
    attn_f16_kernel<<<ga, 256>>>(q, k, v, ctx);

    // 4) output projection
    dim3 gg(DM / 128, MROWS / 64);         // (8, 64)
    gemm_f16_kernel<0><<<gg, 128, GSM>>>(ctx, wh + (size_t)3 * DM * DM,
                                         bo, nullptr, nullptr,
                                         nullptr, nullptr, nullptr, out);
}

// round 17
// speedup vs baseline: 1.1510x; 1.0667x over previous
#include <cuda_runtime.h>
#include <cuda_fp16.h>
#include <cstdint>

// ---------------------------------------------------------------------------
// MultiHeadAttention, fp16 tensor cores (m16n8k16, fp32 accum) + ldmatrix +
// cp.async.  B=2, S=2048, D=1024, H=16, d=64.
// R17: GEMM restored to R11-exact (measured best: 39us out-proj, 287 total).
// Attention: KV pipeline deepened 2->4 stages (dynamic smem 73.7KB,
// wait<2> instead of wait<0>) -- everything else identical to R11.
// ---------------------------------------------------------------------------

constexpr int S_LEN = 2048;
constexpr int DM    = 1024;
constexpr int NH    = 16;
constexpr int HD    = 64;
constexpr int BATCH = 2;
constexpr int MROWS = BATCH * S_LEN;   // 4096

__device__ __half g_xh [(size_t)MROWS * DM];
__device__ __half g_wh [(size_t)4 * DM * DM];
__device__ __half g_q  [(size_t)BATCH * NH * S_LEN * HD];   // pre-scaled 1/8
__device__ __half g_k  [(size_t)BATCH * NH * S_LEN * HD];
__device__ __half g_v  [(size_t)BATCH * NH * S_LEN * HD];
__device__ __half g_ctx[(size_t)MROWS * DM];

__device__ __forceinline__ void mma_f16(float* c, const uint32_t* a, const uint32_t* b) {
    asm volatile(
        "mma.sync.aligned.m16n8k16.row.col.f32.f16.f16.f32 "
        "{%0,%1,%2,%3}, {%4,%5,%6,%7}, {%8,%9}, {%0,%1,%2,%3};"
        : "+f"(c[0]), "+f"(c[1]), "+f"(c[2]), "+f"(c[3])
        : "r"(a[0]), "r"(a[1]), "r"(a[2]), "r"(a[3]), "r"(b[0]), "r"(b[1]));
}
__device__ __forceinline__ void ldsm_x4(uint32_t* r, uint32_t addr) {
    asm volatile("ldmatrix.sync.aligned.m8n8.x4.shared.b16 {%0,%1,%2,%3}, [%4];"
        : "=r"(r[0]), "=r"(r[1]), "=r"(r[2]), "=r"(r[3]) : "r"(addr));
}
__device__ __forceinline__ void ldsm_x4_t(uint32_t* r, uint32_t addr) {
    asm volatile("ldmatrix.sync.aligned.m8n8.x4.trans.shared.b16 {%0,%1,%2,%3}, [%4];"
        : "=r"(r[0]), "=r"(r[1]), "=r"(r[2]), "=r"(r[3]) : "r"(addr));
}
__device__ __forceinline__ void cp_async16(uint32_t smem, const void* g) {
    asm volatile("cp.async.cg.shared.global [%0], [%1], 16;" :: "r"(smem), "l"(g));
}
__device__ __forceinline__ void cp_commit() { asm volatile("cp.async.commit_group;"); }
template<int N> __device__ __forceinline__ void cp_wait() {
    asm volatile("cp.async.wait_group %0;" :: "n"(N));
}
__device__ __forceinline__ uint32_t pack_h2(float a, float b) {
    __half2 h = __floats2half2_rn(a, b);
    return *reinterpret_cast<uint32_t*>(&h);
}

// ---------------------------------------------------------------------------
// Convert x + weights to fp16.  8 floats per thread.
// ---------------------------------------------------------------------------
__global__ void __launch_bounds__(256)
convert_kernel(const float* __restrict__ x,  const float* __restrict__ wq,
               const float* __restrict__ wk, const float* __restrict__ wv,
               const float* __restrict__ wo)
{
    constexpr size_t NX = (size_t)MROWS * DM;      // 4M
    constexpr size_t NW = (size_t)DM * DM;         // 1M
    const size_t i8 = ((size_t)blockIdx.x * 256 + threadIdx.x) * 8;
    const float* src;
    __half* dst;
    if (i8 < NX) { src = x + i8; dst = g_xh + i8; }
    else {
        const size_t r = i8 - NX;
        const int t = (int)(r / NW);
        const size_t off = r % NW;
        src = ((t == 0) ? wq : (t == 1) ? wk : (t == 2) ? wv : wo) + off;
        dst = g_wh + (size_t)t * NW + off;
    }
    float4 a = *(const float4*)(src);
    float4 b = *(const float4*)(src + 4);
    __half2 h[4];
    h[0] = __floats2half2_rn(a.x, a.y); h[1] = __floats2half2_rn(a.z, a.w);
    h[2] = __floats2half2_rn(b.x, b.y); h[3] = __floats2half2_rn(b.z, b.w);
    *(uint4*)dst = *(uint4*)h;
}

// ---------------------------------------------------------------------------
// GEMM fp16 (R11-exact): C[4096,1024] = A @ W + bias.  128x128 block,
// 8 warps (2x4), warp 64x32, BK=32 x 4 stages, cadence:
// wait<2> -> sync -> issue kt+3 -> compute kt.
// MODE 0: fp32 row-major out.  MODE 1: merged QKV, half head-split out,
// z==0 scaled 1/8.
// ---------------------------------------------------------------------------
struct GemmSmem {
    __half A[4][128][40];     // pad 40: ldmatrix conflict-free
    __half B[4][32][136];     // pad 136: conflict-free
};

template<int MODE>
__global__ void __launch_bounds__(256)
gemm_f16_kernel(const __half* __restrict__ Ag, const __half* __restrict__ Wall,
                const float* __restrict__ b0, const float* __restrict__ b1,
                const float* __restrict__ b2,
                __half* __restrict__ o0, __half* __restrict__ o1,
                __half* __restrict__ o2, float* __restrict__ fout)
{
    constexpr int K = DM, N = DM;
    extern __shared__ char smem_raw[];
    GemmSmem& s = *reinterpret_cast<GemmSmem*>(smem_raw);

    const int tid  = threadIdx.x;
    const int warp = tid >> 5, lane = tid & 31;
    const int g    = lane >> 2, tg = lane & 3;
    const int wr   = warp >> 2;            // 0..1
    const int wc   = warp & 3;             // 0..3
    const int brow = blockIdx.y * 128;
    const int bcol = blockIdx.x * 128;
    const int z    = (MODE == 1) ? blockIdx.z : 0;

    const __half* W    = (MODE == 1) ? (Wall + (size_t)z * DM * DM) : Wall;
    const float* bias  = (MODE == 1) ? ((z == 0) ? b0 : (z == 1) ? b1 : b2) : b0;
    __half* outh       = (MODE == 1) ? ((z == 0) ? o0 : (z == 1) ? o1 : o2) : o0;
    const float oscale = (MODE == 1 && z == 0) ? 0.125f : 1.0f;

    const uint32_t sA = (uint32_t)__cvta_generic_to_shared(&s.A[0][0][0]);
    const uint32_t sB = (uint32_t)__cvta_generic_to_shared(&s.B[0][0][0]);
    constexpr uint32_t A_STAGE = 128 * 40 * 2;   // 10240
    constexpr uint32_t B_STAGE = 32 * 136 * 2;   // 8704

    const int ca0 = tid * 2;
    const int cb0 = tid * 2;

    auto issue = [&](int kt) {
        const uint32_t st = (uint32_t)(kt & 3);
#pragma unroll
        for (int i = 0; i < 2; i++) {
            const int ca = ca0 + i, row = ca >> 2, c8 = (ca & 3) * 8;
            cp_async16(sA + st * A_STAGE + (uint32_t)(row * 40 + c8) * 2,
                       Ag + (size_t)(brow + row) * K + kt * 32 + c8);
            const int cb = cb0 + i, rb = cb >> 4, n8 = (cb & 15) * 8;
            cp_async16(sB + st * B_STAGE + (uint32_t)(rb * 136 + n8) * 2,
                       W + (size_t)(kt * 32 + rb) * N + bcol + n8);
        }
    };

    float acc[4][4][4];
#pragma unroll
    for (int mt = 0; mt < 4; mt++)
#pragma unroll
        for (int nt = 0; nt < 4; nt++)
#pragma unroll
            for (int i = 0; i < 4; i++) acc[mt][nt][i] = 0.f;

    issue(0); cp_commit();
    issue(1); cp_commit();
    issue(2); cp_commit();

    constexpr int NCHUNK = K / 32;         // 32
    for (int kt = 0; kt < NCHUNK; kt++) {
        cp_wait<2>();
        __syncthreads();
        if (kt + 3 < NCHUNK) issue(kt + 3);
        cp_commit();

        const uint32_t st = (uint32_t)(kt & 3);
        const uint32_t aBase = sA + st * A_STAGE;
        const uint32_t bBase = sB + st * B_STAGE;

#pragma unroll
        for (int ks = 0; ks < 2; ks++) {
            uint32_t a[4][4];
#pragma unroll
            for (int mt = 0; mt < 4; mt++) {
                const int r = wr * 64 + mt * 16 + (lane & 15);
                const int c = ks * 16 + (lane >> 4) * 8;
                ldsm_x4(a[mt], aBase + (uint32_t)(r * 40 + c) * 2);
            }
            uint32_t b[4][2];
#pragma unroll
            for (int ntp = 0; ntp < 2; ntp++) {
                uint32_t bb[4];
                const int rk = ks * 16 + (lane & 15);
                const int nn = wc * 32 + ntp * 16 + (lane >> 4) * 8;
                ldsm_x4_t(bb, bBase + (uint32_t)(rk * 136 + nn) * 2);
                b[2 * ntp][0] = bb[0]; b[2 * ntp][1] = bb[1];
                b[2 * ntp + 1][0] = bb[2]; b[2 * ntp + 1][1] = bb[3];
            }
#pragma unroll
            for (int mt = 0; mt < 4; mt++)
#pragma unroll
                for (int nt = 0; nt < 4; nt++)
                    mma_f16(acc[mt][nt], a[mt], b[nt]);
        }
    }

    // epilogue
#pragma unroll
    for (int mt = 0; mt < 4; mt++) {
#pragma unroll
        for (int nt = 0; nt < 4; nt++) {
#pragma unroll
            for (int half = 0; half < 2; half++) {
                const int m = brow + wr * 64 + mt * 16 + g + half * 8;
                const int n = bcol + wc * 32 + nt * 8 + 2 * tg;
                const float v0 = (acc[mt][nt][half * 2 + 0] + bias[n])     * oscale;
                const float v1 = (acc[mt][nt][half * 2 + 1] + bias[n + 1]) * oscale;
                if (MODE == 0) {
                    *(float2*)&fout[(size_t)m * N + n] = make_float2(v0, v1);
                } else {
                    const int bb = m >> 11, sidx = m & 2047;
                    const int h  = n >> 6,  dd = n & 63;
                    *(uint32_t*)&outh[(((size_t)(bb * NH + h) * S_LEN) + sidx) * HD + dd]
                        = pack_h2(v0, v1);
                }
            }
        }
    }
}

// ---------------------------------------------------------------------------
// Flash attention fp16.  Block = 128 q x head x batch, 8 warps; each warp
// owns 16 q-rows x FULL kv tile -> softmax entirely warp-local.
// R17: KV tiles now 4-stage (dynamic smem 73.7KB), prefetch distance 3,
// wait<2>.  All fragment/softmax code identical to R11.
// ---------------------------------------------------------------------------
struct AttnSmem {
    __half K[4][64][72];
    __half V[4][64][72];
};

__global__ void __launch_bounds__(256, 2)
attn_f16_kernel(const __half* __restrict__ Q, const __half* __restrict__ Km,
                const __half* __restrict__ Vm, __half* __restrict__ ctx)
{
    extern __shared__ char smem_raw[];
    AttnSmem& s = *reinterpret_cast<AttnSmem*>(smem_raw);

    const int tid  = threadIdx.x;
    const int warp = tid >> 5, lane = tid & 31;
    const int g    = lane >> 2, tg = lane & 3;
    const int qt0  = blockIdx.x * 128;
    const int h    = blockIdx.y;
    const int b    = blockIdx.z;
    const size_t head_base = (size_t)(b * NH + h) * S_LEN * HD;

    const __half* Kg = Km + head_base;
    const __half* Vg = Vm + head_base;

    uint32_t qa[4][4];
    {
        const __half* q0 = Q + head_base + (size_t)(qt0 + warp * 16 + g) * HD;
        const __half* q1 = q0 + 8 * HD;
#pragma unroll
        for (int ks = 0; ks < 4; ks++) {
            qa[ks][0] = *(const uint32_t*)&q0[ks * 16 + 2 * tg];
            qa[ks][1] = *(const uint32_t*)&q1[ks * 16 + 2 * tg];
            qa[ks][2] = *(const uint32_t*)&q0[ks * 16 + 8 + 2 * tg];
            qa[ks][3] = *(const uint32_t*)&q1[ks * 16 + 8 + 2 * tg];
        }
    }

    float m0 = -1e30f, m1 = -1e30f;
    float l0 = 0.f, l1 = 0.f;
    float oa[8][4];
#pragma unroll
    for (int nt = 0; nt < 8; nt++)
#pragma unroll
        for (int i = 0; i < 4; i++) oa[nt][i] = 0.f;

    const uint32_t sK = (uint32_t)__cvta_generic_to_shared(&s.K[0][0][0]);
    const uint32_t sV = (uint32_t)__cvta_generic_to_shared(&s.V[0][0][0]);
    constexpr uint32_t KV_STAGE = 64 * 72 * 2;   // 9216 per stage
    constexpr int NTILE = S_LEN / 64;            // 32

    auto issue = [&](int kt) {
        const uint32_t st = (uint32_t)(kt & 3);
        const int base = kt * 64;
#pragma unroll
        for (int i = 0; i < 2; i++) {
            const int idx = tid * 2 + i;
            const int row = idx >> 3, c8 = (idx & 7) * 8;
            const size_t goff = (size_t)(base + row) * HD + c8;
            const uint32_t soff = (uint32_t)(row * 72 + c8) * 2;
            cp_async16(sK + st * KV_STAGE + soff, Kg + goff);
            cp_async16(sV + st * KV_STAGE + soff, Vg + goff);
        }
    };

    issue(0); cp_commit();
    issue(1); cp_commit();
    issue(2); cp_commit();

    for (int kt = 0; kt < NTILE; kt++) {
        cp_wait<2>();                      // tile kt resident (<=2 newer pending)
        __syncthreads();                   // all warps past tile kt-1; slot free
        if (kt + 3 < NTILE) issue(kt + 3);
        cp_commit();

        const uint32_t st = (uint32_t)(kt & 3);
        const uint32_t kBase = sK + st * KV_STAGE;
        const uint32_t vBase = sV + st * KV_STAGE;

        float sa[8][4];
#pragma unroll
        for (int nt = 0; nt < 8; nt++)
#pragma unroll
            for (int i = 0; i < 4; i++) sa[nt][i] = 0.f;
#pragma unroll
        for (int p = 0; p < 2; p++) {
#pragma unroll
            for (int nt = 0; nt < 8; nt++) {
                uint32_t kb[4];
                const int kvr = nt * 8 + (lane & 7);
                const int d   = p * 32 + (lane >> 3) * 8;
                ldsm_x4(kb, kBase + (uint32_t)(kvr * 72 + d) * 2);
                mma_f16(sa[nt], qa[2 * p],     kb);
                mma_f16(sa[nt], qa[2 * p + 1], kb + 2);
            }
        }

        float pm0 = -1e30f, pm1 = -1e30f;
#pragma unroll
        for (int nt = 0; nt < 8; nt++) {
            pm0 = fmaxf(pm0, fmaxf(sa[nt][0], sa[nt][1]));
            pm1 = fmaxf(pm1, fmaxf(sa[nt][2], sa[nt][3]));
        }
        pm0 = fmaxf(pm0, __shfl_xor_sync(0xffffffffu, pm0, 1));
        pm0 = fmaxf(pm0, __shfl_xor_sync(0xffffffffu, pm0, 2));
        pm1 = fmaxf(pm1, __shfl_xor_sync(0xffffffffu, pm1, 1));
        pm1 = fmaxf(pm1, __shfl_xor_sync(0xffffffffu, pm1, 2));

        const float mnew0 = fmaxf(m0, pm0);
        const float mnew1 = fmaxf(m1, pm1);
        const float sc0 = __expf(m0 - mnew0);
        const float sc1 = __expf(m1 - mnew1);

        float ps0 = 0.f, ps1 = 0.f;
#pragma unroll
        for (int nt = 0; nt < 8; nt++) {
            sa[nt][0] = __expf(sa[nt][0] - mnew0);
            sa[nt][1] = __expf(sa[nt][1] - mnew0);
            sa[nt][2] = __expf(sa[nt][2] - mnew1);
            sa[nt][3] = __expf(sa[nt][3] - mnew1);
            ps0 += sa[nt][0] + sa[nt][1];
            ps1 += sa[nt][2] + sa[nt][3];
        }
        ps0 += __shfl_xor_sync(0xffffffffu, ps0, 1);
        ps0 += __shfl_xor_sync(0xffffffffu, ps0, 2);
        ps1 += __shfl_xor_sync(0xffffffffu, ps1, 1);
        ps1 += __shfl_xor_sync(0xffffffffu, ps1, 2);

        l0 = l0 * sc0 + ps0;
        l1 = l1 * sc1 + ps1;
        m0 = mnew0; m1 = mnew1;
#pragma unroll
        for (int nt = 0; nt < 8; nt++) {
            oa[nt][0] *= sc0; oa[nt][1] *= sc0;
            oa[nt][2] *= sc1; oa[nt][3] *= sc1;
        }

#pragma unroll
        for (int p = 0; p < 4; p++) {
            uint32_t pa[4];
            pa[0] = pack_h2(sa[2 * p][0],     sa[2 * p][1]);
            pa[1] = pack_h2(sa[2 * p][2],     sa[2 * p][3]);
            pa[2] = pack_h2(sa[2 * p + 1][0], sa[2 * p + 1][1]);
            pa[3] = pack_h2(sa[2 * p + 1][2], sa[2 * p + 1][3]);
#pragma unroll
            for (int ntp = 0; ntp < 4; ntp++) {
                uint32_t vb[4];
                const int kvr = p * 16 + (lane & 15);
                const int d   = ntp * 16 + (lane >> 4) * 8;
                ldsm_x4_t(vb, vBase + (uint32_t)(kvr * 72 + d) * 2);
                mma_f16(oa[2 * ntp],     pa, vb);
                mma_f16(oa[2 * ntp + 1], pa, vb + 2);
            }
        }
    }

    const float inv0 = 1.f / l0;
    const float inv1 = 1.f / l1;
    __half* c0p = ctx + ((size_t)(b * S_LEN) + qt0 + warp * 16 + g) * DM + h * HD;
    __half* c1p = c0p + 8 * DM;
#pragma unroll
    for (int nt = 0; nt < 8; nt++) {
        const int c = nt * 8 + 2 * tg;
        *(uint32_t*)&c0p[c] = pack_h2(oa[nt][0] * inv0, oa[nt][1] * inv0);
        *(uint32_t*)&c1p[c] = pack_h2(oa[nt][2] * inv1, oa[nt][3] * inv1);
    }
}

// ---------------------------------------------------------------------------
extern "C" void kernel_launch(void* const* d_in, const int* in_sizes, int n_in,
                              void* d_out, int out_size)
{
    const float* x  = (const float*)d_in[0];
    const float* wq = (const float*)d_in[1];
    const float* bq = (const float*)d_in[2];
    const float* wk = (const float*)d_in[3];
    const float* bk = (const float*)d_in[4];
    const float* wv = (const float*)d_in[5];
    const float* bv = (const float*)d_in[6];
    const float* wo = (const float*)d_in[7];
    const float* bo = (const float*)d_in[8];
    float* out = (float*)d_out;

    __half *xh, *wh, *q, *k, *v, *ctx;
    cudaGetSymbolAddress((void**)&xh,  g_xh);
    cudaGetSymbolAddress((void**)&wh,  g_wh);
    cudaGetSymbolAddress((void**)&q,   g_q);
    cudaGetSymbolAddress((void**)&k,   g_k);
    cudaGetSymbolAddress((void**)&v,   g_v);
    cudaGetSymbolAddress((void**)&ctx, g_ctx);

    constexpr int GSM = (int)sizeof(GemmSmem);
    constexpr int ASM = (int)sizeof(AttnSmem);
    cudaFuncSetAttribute(gemm_f16_kernel<0>,
                         cudaFuncAttributeMaxDynamicSharedMemorySize, GSM);
    cudaFuncSetAttribute(gemm_f16_kernel<1>,
                         cudaFuncAttributeMaxDynamicSharedMemorySize, GSM);
    cudaFuncSetAttribute(attn_f16_kernel,
                         cudaFuncAttributeMaxDynamicSharedMemorySize, ASM);

    // 1) fp16 conversion
    constexpr int NCONV = (int)(((size_t)MROWS * DM + 4 * (size_t)DM * DM) / 8);
    convert_kernel<<<NCONV / 256, 256>>>(x, wq, wk, wv, wo);

    // 2) merged QKV projection
    dim3 gqkv(DM / 128, MROWS / 128, 3);
    gemm_f16_kernel<1><<<gqkv, 256, GSM>>>(xh, wh, bq, bk, bv, q, k, v, nullptr);

    // 3) flash attention (128 q-rows per block, 4-stage KV pipeline)
    dim3 ga(S_LEN / 128, NH, BATCH);
    attn_f16_kernel<<<ga, 256, ASM>>>(q, k, v, ctx);

    // 4) output projection
    dim3 gg(DM / 128, MROWS / 128);
    gemm_f16_kernel<0><<<gg, 256, GSM>>>(ctx, wh + (size_t)3 * DM * DM,
                                         bo, nullptr, nullptr,
                                         nullptr, nullptr, nullptr, out);
}